// round 17
// baseline (speedup 1.0000x reference)
#include <cuda_runtime.h>
#include <stdint.h>

// out[k,l] = sum_j mitchell_mul(x[k,j], weight[l,j]) + bias[l]
// Mitchell approx multiply == integer add of offset float bit patterns:
//   packed(v) = (sign<<31) | max(bits(|v|) - 0x1FC00000, 0)
//   mitchell(a,b) = reinterpret_float(packed(a) + packed(b))
// (low fields < 2^30 for these inputs -> no carry into the sign bit; signs XOR)
//
// R17: slot-density round. 8x8 thread tile (BM=BN=128): 4 LDS.128 per 64 MACs
// (vs 3 per 32), loop overhead amortized over 128-add runs. Grid (4,4,37) =
// 592 CTAs = exactly 2 waves at occupancy 2. Same balanced 37-slice split-K
// (34x28 + 3x24 k), zero-padded planes, REDG.128 into bias-prefilled out.

#define NROWS 512
#define MROWS 512
#define KDIM  1024
#define ZSLICES 37
#define KMAX 28              // k planes per slice (28 or 24 valid)
#define KQ   7               // quads per slice
#define BM 128               // x rows per CTA
#define BN 128               // w rows per CTA
#define PADM (BM + 4)
#define PADN (BN + 4)
#define TM 8
#define TN 8

__device__ __forceinline__ unsigned int pack1(unsigned int b) {
    unsigned int mag = b & 0x7FFFFFFFu;
    unsigned int low = (mag > 0x1FC00000u) ? (mag - 0x1FC00000u) : 0u;
    return (b & 0x80000000u) | low;
}

__global__ __launch_bounds__(256) void prefill_kernel(
    const float* __restrict__ bias, float* __restrict__ out) {
    int i4 = blockIdx.x * blockDim.x + threadIdx.x;   // 0..65535 float4s
    reinterpret_cast<float4*>(out)[i4] =
        reinterpret_cast<const float4*>(bias)[i4 & (MROWS / 4 - 1)];
}

__global__ __launch_bounds__(256, 2) void mitchell_mm_kernel(
    const uint4* __restrict__ xq, const uint4* __restrict__ wq,
    float* __restrict__ out) {
    __shared__ unsigned int Xs[KMAX][PADM];   // [k][row] 14784 B
    __shared__ unsigned int Ws[KMAX][PADN];   //          14784 B

    const int tid = threadIdx.x;            // 256 threads: 16 x 16
    const int tx = tid & 15;                // col group (TN=8)
    const int ty = tid >> 4;                // row group (TM=8)
    const int rowBase = blockIdx.y * BM;
    const int colBase = blockIdx.x * BN;
    const int z = blockIdx.z;
    // 34 slices of 28 k, then 3 slices of 24 k (34*28 + 3*24 = 1024).
    const int kBase = (z < 34) ? 28 * z : 952 + 24 * (z - 34);
    const int kcq   = (z < 34) ? 7 : 6;     // valid quads this slice
    const int K4 = KDIM / 4;
    const int g0 = kBase / 4;               // kBase % 4 == 0 always

    // ---- Staging: 2 threads per row; thread handles quads q = kq2, kq2+2, ...
    //      X rows 0..127 and W rows 0..127 (128 rows each, 7 quads).
    const int srow = tid >> 1;              // 0..127
    const int kq2  = tid & 1;               // 0..1

    const uint4 zv = make_uint4(0u, 0u, 0u, 0u);
#pragma unroll
    for (int q = 0; q < KQ; q++) {
        if ((q & 1) == kq2) {
            bool valid = (q < kcq);
            uint4 x0 = valid ? xq[(rowBase + srow) * K4 + g0 + q] : zv;
            uint4 w0 = valid ? wq[(colBase + srow) * K4 + g0 + q] : zv;
            Xs[q * 4 + 0][srow] = pack1(x0.x);
            Xs[q * 4 + 1][srow] = pack1(x0.y);
            Xs[q * 4 + 2][srow] = pack1(x0.z);
            Xs[q * 4 + 3][srow] = pack1(x0.w);
            Ws[q * 4 + 0][srow] = pack1(w0.x);
            Ws[q * 4 + 1][srow] = pack1(w0.y);
            Ws[q * 4 + 2][srow] = pack1(w0.z);
            Ws[q * 4 + 3][srow] = pack1(w0.w);
        }
    }
    __syncthreads();

    // ---- Uniform 28-iteration MAC loop, 8x8 per thread.
    float acc[TM][TN];
#pragma unroll
    for (int i = 0; i < TM; i++)
#pragma unroll
        for (int j = 0; j < TN; j++) acc[i][j] = 0.0f;

#pragma unroll 7
    for (int k = 0; k < KMAX; k++) {
        uint4 a0 = *reinterpret_cast<const uint4*>(&Xs[k][ty * TM]);
        uint4 a1 = *reinterpret_cast<const uint4*>(&Xs[k][ty * TM + 4]);
        uint4 b0 = *reinterpret_cast<const uint4*>(&Ws[k][tx * TN]);
        uint4 b1 = *reinterpret_cast<const uint4*>(&Ws[k][tx * TN + 4]);
        unsigned int a[TM] = {a0.x, a0.y, a0.z, a0.w, a1.x, a1.y, a1.z, a1.w};
        unsigned int b[TN] = {b0.x, b0.y, b0.z, b0.w, b1.x, b1.y, b1.z, b1.w};
#pragma unroll
        for (int i = 0; i < TM; i++)
#pragma unroll
            for (int j = 0; j < TN; j++)
                acc[i][j] += __uint_as_float(a[i] + b[j]);
    }

    // ---- Fused split-K reduction: vector REDG.128 into bias-prefilled out.
#pragma unroll
    for (int i = 0; i < TM; i++) {
        int r = rowBase + ty * TM + i;
        atomicAdd(reinterpret_cast<float4*>(&out[r * MROWS + colBase + tx * TN]),
                  make_float4(acc[i][0], acc[i][1], acc[i][2], acc[i][3]));
        atomicAdd(reinterpret_cast<float4*>(&out[r * MROWS + colBase + tx * TN + 4]),
                  make_float4(acc[i][4], acc[i][5], acc[i][6], acc[i][7]));
    }
}

extern "C" void kernel_launch(void* const* d_in, const int* in_sizes, int n_in,
                              void* d_out, int out_size) {
    const float* x    = (const float*)d_in[0];
    const float* w    = (const float*)d_in[1];
    const float* bias = (const float*)d_in[2];
    float* out = (float*)d_out;

    prefill_kernel<<<NROWS * MROWS / 4 / 256, 256>>>(bias, out);

    dim3 grid(MROWS / BN, NROWS / BM, ZSLICES);   // (4,4,37) = 592 CTAs
    mitchell_mm_kernel<<<grid, 256>>>((const uint4*)x, (const uint4*)w, out);
}